// round 3
// baseline (speedup 1.0000x reference)
#include <cuda_runtime.h>
#include <cstdint>

// SNN forward: x[B,5] -> L1(32) -> spike(pre>=2) -> L2(32) -> L3(16) -> L4(10) -> spike
// L1 dense in packed f32x2 (FFMA2). Layers 2-4 provably all-zero unless
// popcount(mask1) >= g_minpop (sound upper bound via max W2 column-max); the
// exact path runs for ~1e-4 of rows and reads W2/W3/W4 straight from L2.

__device__ float4 g_w1p[40];   // [q*5+k] = (W1[4q+0][k], W1[4q+1][k], W1[4q+2][k], W1[4q+3][k])
__device__ int    g_minpop;

__global__ void setup_kernel(const float* __restrict__ W1,
                             const float* __restrict__ W2)
{
    int t = threadIdx.x;
    if (t < 40) {
        int q = t / 5, k = t % 5;
        float4 v;
        v.x = W1[(4 * q + 0) * 5 + k];
        v.y = W1[(4 * q + 1) * 5 + k];
        v.z = W1[(4 * q + 2) * 5 + k];
        v.w = W1[(4 * q + 3) * 5 + k];
        g_w1p[t] = v;
    }
    if (t >= 32 && t < 64) {
        int i = t - 32;
        float mx = W2[i];
        #pragma unroll
        for (int j = 1; j < 32; j++) mx = fmaxf(mx, W2[j * 32 + i]);
        #pragma unroll
        for (int s = 16; s > 0; s >>= 1)
            mx = fmaxf(mx, __shfl_xor_sync(0xffffffffu, mx, s));
        if (i == 0) {
            // smallest k such that k*cmax >= 1.99 (conservative: acc2 <= popc*cmax,
            // and any fp-computed acc2 that could round to >=2 forces the exact path)
            int mp = 1;
            while (mp < 33 && (float)mp * mx < 1.99f) mp++;
            g_minpop = mp;
        }
    }
}

// ---- packed f32x2 helpers ----
__device__ __forceinline__ unsigned long long pk2(float v) {
    unsigned long long r;
    asm("mov.b64 %0, {%1,%2};" : "=l"(r) : "f"(v), "f"(v));
    return r;
}
__device__ __forceinline__ unsigned long long mul2(unsigned long long a, unsigned long long b) {
    unsigned long long d;
    asm("mul.rn.f32x2 %0, %1, %2;" : "=l"(d) : "l"(a), "l"(b));
    return d;
}
__device__ __forceinline__ unsigned long long fma2(unsigned long long a, unsigned long long b,
                                                   unsigned long long c) {
    unsigned long long d;
    asm("fma.rn.f32x2 %0, %1, %2, %3;" : "=l"(d) : "l"(a), "l"(b), "l"(c));
    return d;
}
__device__ __forceinline__ void unpk(unsigned long long v, float& lo, float& hi) {
    asm("mov.b64 {%0,%1}, %2;" : "=f"(lo), "=f"(hi) : "l"(v));
}

// exact layers 2-4 (rare). Increasing-i gather == full dot with zero terms skipped
// (exact in fp32), validated rel_err==0 in prior rounds.
__device__ __noinline__ unsigned rare_path(unsigned mask1,
                                           const float* __restrict__ W2,
                                           const float* __restrict__ W3,
                                           const float* __restrict__ W4)
{
    unsigned mask2 = 0;
    #pragma unroll
    for (int jc = 0; jc < 32; jc += 8) {
        float acc[8] = {0, 0, 0, 0, 0, 0, 0, 0};
        unsigned mm = mask1;
        while (mm) {
            int i = __ffs(mm) - 1; mm &= mm - 1;
            #pragma unroll
            for (int j = 0; j < 8; j++) acc[j] += W2[(jc + j) * 32 + i];
        }
        #pragma unroll
        for (int j = 0; j < 8; j++)
            if (acc[j] >= 2.0f) mask2 |= 1u << (jc + j);
    }
    if (!mask2) return 0;

    unsigned mask3 = 0;
    #pragma unroll
    for (int jc = 0; jc < 16; jc += 8) {
        float acc[8] = {0, 0, 0, 0, 0, 0, 0, 0};
        unsigned mm = mask2;
        while (mm) {
            int i = __ffs(mm) - 1; mm &= mm - 1;
            #pragma unroll
            for (int j = 0; j < 8; j++) acc[j] += W3[(jc + j) * 32 + i];
        }
        #pragma unroll
        for (int j = 0; j < 8; j++)
            if (acc[j] >= 2.0f) mask3 |= 1u << (jc + j);
    }
    if (!mask3) return 0;

    float acc4[10];
    #pragma unroll
    for (int j = 0; j < 10; j++) acc4[j] = 0.0f;
    unsigned mm = mask3;
    while (mm) {
        int i = __ffs(mm) - 1; mm &= mm - 1;
        #pragma unroll
        for (int j = 0; j < 10; j++) acc4[j] += W4[j * 16 + i];
    }
    unsigned om = 0;
    #pragma unroll
    for (int j = 0; j < 10; j++)
        if (acc4[j] >= 2.0f) om |= 1u << j;
    return om;
}

#define BT 256
#define RPB 512   // rows per block (2 per thread)

__global__ __launch_bounds__(BT)
void snn_kernel(const float* __restrict__ x,
                const float* __restrict__ W2,
                const float* __restrict__ W3,
                const float* __restrict__ W4,
                float* __restrict__ out)
{
    __shared__ float4 sW[40];
    __shared__ float  sX[RPB * 5];   // 2560 floats

    const int tid = threadIdx.x;
    const size_t rowbase = (size_t)blockIdx.x * RPB;
    const int minpop = g_minpop;

    if (tid < 40) sW[tid] = g_w1p[tid];

    // stage x tile: 640 float4, coalesced
    {
        const float4* xv = reinterpret_cast<const float4*>(x) + rowbase * 5 / 4;
        float4* sx4 = reinterpret_cast<float4*>(sX);
        #pragma unroll
        for (int i = tid; i < RPB * 5 / 4; i += BT) sx4[i] = xv[i];
    }
    // zero-fill output tile: 1280 float4, coalesced (rare scatter overwrites after sync)
    {
        float4* ov = reinterpret_cast<float4*>(out + rowbase * 10);
        const float4 z = make_float4(0.f, 0.f, 0.f, 0.f);
        #pragma unroll
        for (int i = tid; i < RPB * 10 / 4; i += BT) ov[i] = z;
    }
    __syncthreads();

    uint32_t swa;
    asm("{ .reg .u64 t; cvta.to.shared.u64 t, %1; cvt.u32.u64 %0, t; }"
        : "=r"(swa) : "l"(sW));

    // two rows per thread: tid and tid+256 (bank-conflict-free: 5 coprime 32)
    unsigned long long xA[5], xB[5];
    #pragma unroll
    for (int k = 0; k < 5; k++) xA[k] = pk2(sX[tid * 5 + k]);
    #pragma unroll
    for (int k = 0; k < 5; k++) xB[k] = pk2(sX[(tid + 256) * 5 + k]);

    unsigned mA = 0, mB = 0;
    #pragma unroll
    for (int q = 0; q < 8; q++) {
        unsigned long long w01[5], w23[5];
        #pragma unroll
        for (int k = 0; k < 5; k++) {
            asm("ld.shared.v2.u64 {%0,%1}, [%2];"
                : "=l"(w01[k]), "=l"(w23[k])
                : "r"(swa + (unsigned)((q * 5 + k) * 16)));
        }
        // row A, outputs 4q..4q+3 (same mul->fma order as reference-validated kernel)
        unsigned long long a01 = mul2(w01[0], xA[0]);
        unsigned long long a23 = mul2(w23[0], xA[0]);
        unsigned long long b01 = mul2(w01[0], xB[0]);
        unsigned long long b23 = mul2(w23[0], xB[0]);
        #pragma unroll
        for (int k = 1; k < 5; k++) {
            a01 = fma2(w01[k], xA[k], a01);
            a23 = fma2(w23[k], xA[k], a23);
            b01 = fma2(w01[k], xB[k], b01);
            b23 = fma2(w23[k], xB[k], b23);
        }
        float l0, l1, l2, l3;
        unpk(a01, l0, l1); unpk(a23, l2, l3);
        if (l0 >= 2.0f) mA |= 1u << (4 * q + 0);
        if (l1 >= 2.0f) mA |= 1u << (4 * q + 1);
        if (l2 >= 2.0f) mA |= 1u << (4 * q + 2);
        if (l3 >= 2.0f) mA |= 1u << (4 * q + 3);
        unpk(b01, l0, l1); unpk(b23, l2, l3);
        if (l0 >= 2.0f) mB |= 1u << (4 * q + 0);
        if (l1 >= 2.0f) mB |= 1u << (4 * q + 1);
        if (l2 >= 2.0f) mB |= 1u << (4 * q + 2);
        if (l3 >= 2.0f) mB |= 1u << (4 * q + 3);
    }

    unsigned omA = 0, omB = 0;
    if (__popc(mA) >= minpop) omA = rare_path(mA, W2, W3, W4);
    if (__popc(mB) >= minpop) omB = rare_path(mB, W2, W3, W4);

    __syncthreads();   // order zero-fill STGs before rare scatter (CTA-scope fence)

    if (omA) {
        float* o = out + (rowbase + tid) * 10;
        #pragma unroll
        for (int j = 0; j < 10; j++) o[j] = ((omA >> j) & 1u) ? 1.0f : 0.0f;
    }
    if (omB) {
        float* o = out + (rowbase + tid + 256) * 10;
        #pragma unroll
        for (int j = 0; j < 10; j++) o[j] = ((omB >> j) & 1u) ? 1.0f : 0.0f;
    }
}

extern "C" void kernel_launch(void* const* d_in, const int* in_sizes, int n_in,
                              void* d_out, int out_size)
{
    const float* x  = (const float*)d_in[0];
    const float* W1 = (const float*)d_in[1];
    const float* W2 = (const float*)d_in[2];
    const float* W3 = (const float*)d_in[3];
    const float* W4 = (const float*)d_in[4];
    float* out = (float*)d_out;

    const int B = in_sizes[0] / 5;        // 2097152
    const int grid = B / RPB;             // 4096

    setup_kernel<<<1, 64>>>(W1, W2);
    snn_kernel<<<grid, BT>>>(x, W2, W3, W4, out);
}